// round 17
// baseline (speedup 1.0000x reference)
#include <cuda_runtime.h>
#include <cuda_fp16.h>
#include <math.h>
#include <stdint.h>

#define NB    8
#define NC    256
#define HID   512
#define NPIX  4096
#define NHEAD 8
#define DHEAD 64

// ---------------- scratch ----------------
__device__ __align__(256) __half g_kh[NB * HID * NPIX];       // exp(k), 33.5 MB
__device__ __align__(256) __half g_wkh[HID * NC];
__device__ __align__(256) __half g_wqh[HID * NC];
__device__ __align__(256) __half g_wwh[NHEAD * NC * NC];      // WW[h] = Wo_h @ Wv_h
__device__ __align__(256) float g_esi[NB * HID];              // 1 / row-sum of expk
__device__ __align__(256) __half g_Tn[NB * NHEAD * DHEAD * NC];  // normalized T, half
__device__ __align__(256) float g_fold[NB * NC * HID];
__device__ __align__(256) float g_comb[NB * NC * NC];

// ---------------- helpers ----------------
__device__ __forceinline__ void mma_f16(float* d, const uint32_t* a, const uint32_t* b) {
    asm volatile(
        "mma.sync.aligned.m16n8k16.row.col.f32.f16.f16.f32 "
        "{%0,%1,%2,%3}, {%4,%5,%6,%7}, {%8,%9}, {%0,%1,%2,%3};"
        : "+f"(d[0]), "+f"(d[1]), "+f"(d[2]), "+f"(d[3])
        : "r"(a[0]), "r"(a[1]), "r"(a[2]), "r"(a[3]), "r"(b[0]), "r"(b[1]));
}

// ---------------- pack weights to half: Wk, Wq ----------------
__global__ void pack_w(const float* __restrict__ Wk, const float* __restrict__ Wq,
                       __half* __restrict__ Wkh, __half* __restrict__ Wqh)
{
    const int i = blockIdx.x * 256 + threadIdx.x;
    Wkh[i] = __float2half_rn(Wk[i]);
    Wqh[i] = __float2half_rn(Wq[i]);
}

// ---------------- WW[h][o][c] = sum_e Wo[o][h*64+e] * Wv[h*64+e][c] ----------------
__global__ void ww_kernel(const float* __restrict__ Wo, const float* __restrict__ Wv,
                          __half* __restrict__ WWh)
{
    const int h = blockIdx.x;
    const int ob = blockIdx.y;
    __shared__ float wo_s[16][64];

    const int tid = threadIdx.x;
    for (int i = tid; i < 1024; i += 256) {
        const int o = i >> 6, e = i & 63;
        wo_s[o][e] = Wo[(size_t)(ob * 16 + o) * HID + h * 64 + e];
    }
    __syncthreads();

    const int c = tid;
    #pragma unroll 1
    for (int o = 0; o < 16; o++) {
        float s = 0.0f;
        #pragma unroll
        for (int e = 0; e < 64; e++)
            s += wo_s[o][e] * Wv[(size_t)(h * 64 + e) * NC + c];
        WWh[(size_t)h * NC * NC + (size_t)(ob * 16 + o) * NC + c] = __float2half_rn(s);
    }
}

// ---------------- row sums of expk: esi[row] = 1 / sum_m expk[row][m] ----------------
// 512 blocks x 256 threads; 8 rows per block, 32 lanes per row.
__global__ void es_kernel(const __half* __restrict__ Kh, float* __restrict__ esi)
{
    const int row = blockIdx.x * 8 + (threadIdx.x >> 5);
    const int lane = threadIdx.x & 31;
    const uint4* p = (const uint4*)(Kh + (size_t)row * NPIX);

    float s = 0.0f;
    #pragma unroll
    for (int i = 0; i < 16; i++) {
        uint4 v = p[lane + 32 * i];
        const uint32_t w[4] = {v.x, v.y, v.z, v.w};
        #pragma unroll
        for (int q = 0; q < 4; q++) {
            float2 f = __half22float2(*(__half2*)&w[q]);
            s += f.x + f.y;
        }
    }
    #pragma unroll
    for (int o = 16; o > 0; o >>= 1) s += __shfl_xor_sync(0xffffffffu, s, o);
    if (lane == 0) esi[row] = 1.0f / s;
}

// ---------------- fp16 mma GEMM (R8-proven), MODE 1 => half C with exp ----------------
template<int AHALF, int BHALF, int MODE>
__global__ __launch_bounds__(256, 2)
void mma_gemm_t(const void* __restrict__ Av, long sA, int lda,
                const void* __restrict__ Bv, long sB, int ldb,
                void* __restrict__ Cv, long sC, int ldc,
                const float* __restrict__ bias, int K, float alpha)
{
    __shared__ uint32_t As32[2][128][20];
    __shared__ uint32_t Bs32[2][16][136];

    const int bb = blockIdx.z;
    const float*  Af = (const float*)Av + (AHALF ? 0 : (size_t)bb * sA);
    const __half* Ah = (const __half*)Av + (AHALF ? (size_t)bb * sA : 0);
    const float*  Bf = (const float*)Bv + (BHALF ? 0 : (size_t)bb * sB);
    const __half* Bh = (const __half*)Bv + (BHALF ? (size_t)bb * sB : 0);

    const int tid = threadIdx.x;
    const int wid = tid >> 5, lid = tid & 31;
    const int g = lid >> 2, t = lid & 3;
    const int wm = (wid >> 2) * 64, wn = (wid & 3) * 32;
    const int m0 = blockIdx.y * 128, n0 = blockIdx.x * 128;

    const int am = tid >> 1;
    const int as = tid & 1;
    const int bk = tid >> 3;
    const int bn8 = (tid & 7) * 16;

    float acc[4][4][4];
    #pragma unroll
    for (int i = 0; i < 4; i++)
        #pragma unroll
        for (int j = 0; j < 4; j++)
            #pragma unroll
            for (int q = 0; q < 4; q++) acc[i][j][q] = 0.0f;

    const int KT = K >> 5;

    float4 aRf[4];
    uint4  aRh0, aRh1;
    float4 bRf[4];
    uint4  bRh0, bRh1;

    auto loadA = [&](int k0) {
        if (AHALF) {
            const __half* ap = Ah + (size_t)(m0 + am) * lda + k0 + as * 16;
            aRh0 = *(const uint4*)(ap);
            aRh1 = *(const uint4*)(ap + 8);
        } else {
            const float* ap = Af + (size_t)(m0 + am) * lda + k0;
            #pragma unroll
            for (int p = 0; p < 4; p++)
                aRf[p] = *(const float4*)(ap + (as + 2 * p) * 4);
        }
    };
    auto loadB = [&](int k0) {
        if (BHALF) {
            const __half* bp = Bh + (size_t)(k0 + bk) * ldb + n0 + bn8;
            bRh0 = *(const uint4*)(bp);
            bRh1 = *(const uint4*)(bp + 8);
        } else {
            const float* bp = Bf + (size_t)(k0 + bk) * ldb + n0 + bn8;
            #pragma unroll
            for (int p = 0; p < 4; p++)
                bRf[p] = *(const float4*)(bp + 4 * p);
        }
    };
    auto storeA = [&](int buf) {
        if (AHALF) {
            const int k2 = as * 8;
            As32[buf][am][k2 + 0] = aRh0.x; As32[buf][am][k2 + 1] = aRh0.y;
            As32[buf][am][k2 + 2] = aRh0.z; As32[buf][am][k2 + 3] = aRh0.w;
            As32[buf][am][k2 + 4] = aRh1.x; As32[buf][am][k2 + 5] = aRh1.y;
            As32[buf][am][k2 + 6] = aRh1.z; As32[buf][am][k2 + 7] = aRh1.w;
        } else {
            #pragma unroll
            for (int p = 0; p < 4; p++) {
                const int k2 = (as + 2 * p) * 2;
                __half2 h0 = __floats2half2_rn(aRf[p].x, aRf[p].y);
                __half2 h1 = __floats2half2_rn(aRf[p].z, aRf[p].w);
                As32[buf][am][k2 + 0] = *(uint32_t*)&h0;
                As32[buf][am][k2 + 1] = *(uint32_t*)&h1;
            }
        }
    };
    auto storeB = [&](int buf) {
        __half* bsh = (__half*)&Bs32[buf][0][0];
        const int base = (bk >> 1) * 272 + (bk & 1);
        if (BHALF) {
            const uint32_t w[8] = {bRh0.x, bRh0.y, bRh0.z, bRh0.w, bRh1.x, bRh1.y, bRh1.z, bRh1.w};
            #pragma unroll
            for (int q = 0; q < 8; q++) {
                __half2 h = *(__half2*)&w[q];
                bsh[base + 2 * (bn8 + 2 * q + 0)] = __low2half(h);
                bsh[base + 2 * (bn8 + 2 * q + 1)] = __high2half(h);
            }
        } else {
            #pragma unroll
            for (int p = 0; p < 4; p++) {
                const int nf = bn8 + 4 * p;
                bsh[base + 2 * (nf + 0)] = __float2half_rn(bRf[p].x);
                bsh[base + 2 * (nf + 1)] = __float2half_rn(bRf[p].y);
                bsh[base + 2 * (nf + 2)] = __float2half_rn(bRf[p].z);
                bsh[base + 2 * (nf + 3)] = __float2half_rn(bRf[p].w);
            }
        }
    };

    loadA(0);
    loadB(0);
    storeA(0);
    storeB(0);
    __syncthreads();

    for (int kt = 0; kt < KT; kt++) {
        const int cur = kt & 1;
        const int nxt = cur ^ 1;
        const bool more = (kt + 1 < KT);

        if (more) {
            loadA((kt + 1) << 5);
            loadB((kt + 1) << 5);
        }

        #pragma unroll
        for (int ks = 0; ks < 2; ks++) {
            const int kk2 = ks * 8;
            uint32_t af[4][4], bf[4][2];
            #pragma unroll
            for (int i = 0; i < 4; i++) {
                const int r = wm + i * 16 + g;
                af[i][0] = As32[cur][r][kk2 + t];
                af[i][1] = As32[cur][r + 8][kk2 + t];
                af[i][2] = As32[cur][r][kk2 + t + 4];
                af[i][3] = As32[cur][r + 8][kk2 + t + 4];
            }
            #pragma unroll
            for (int j = 0; j < 4; j++) {
                const int c = wn + j * 8 + g;
                bf[j][0] = Bs32[cur][kk2 + t][c];
                bf[j][1] = Bs32[cur][kk2 + t + 4][c];
            }
            #pragma unroll
            for (int i = 0; i < 4; i++)
                #pragma unroll
                for (int j = 0; j < 4; j++)
                    mma_f16(acc[i][j], af[i], bf[j]);
        }

        if (more) {
            storeA(nxt);
            storeB(nxt);
        }
        __syncthreads();
    }

    if (MODE == 0) {
        float* C = (float*)Cv + (size_t)bb * sC;
        #pragma unroll
        for (int i = 0; i < 4; i++) {
            const int r0 = m0 + wm + i * 16 + g;
            const int r1 = r0 + 8;
            const float bi0 = bias ? bias[r0] : 0.0f;
            const float bi1 = bias ? bias[r1] : 0.0f;
            #pragma unroll
            for (int j = 0; j < 4; j++) {
                const int col = n0 + wn + j * 8 + 2 * t;
                float2 o0 = make_float2(acc[i][j][0] * alpha + bi0, acc[i][j][1] * alpha + bi0);
                float2 o1 = make_float2(acc[i][j][2] * alpha + bi1, acc[i][j][3] * alpha + bi1);
                *(float2*)(C + (size_t)r0 * ldc + col) = o0;
                *(float2*)(C + (size_t)r1 * ldc + col) = o1;
            }
        }
    } else {
        __half* C = (__half*)Cv + (size_t)bb * sC;
        #pragma unroll
        for (int i = 0; i < 4; i++) {
            const int r0 = m0 + wm + i * 16 + g;
            const int r1 = r0 + 8;
            #pragma unroll
            for (int j = 0; j < 4; j++) {
                const int col = n0 + wn + j * 8 + 2 * t;
                float4 v = make_float4(expf(acc[i][j][0]), expf(acc[i][j][1]),
                                       expf(acc[i][j][2]), expf(acc[i][j][3]));
                *(__half2*)(C + (size_t)r0 * ldc + col) = __floats2half2_rn(v.x, v.y);
                *(__half2*)(C + (size_t)r1 * ldc + col) = __floats2half2_rn(v.z, v.w);
            }
        }
    }
}

// ---------------- T direct: Tn[bh][d][c] = esi[dk] * sum_m expk[dk,m]*cin[c,m] ----------------
// grid (8 heads, 4 c-tiles of 64, NB). 64x64 tile, full K=4096. R8-ctx-proven inner loop.
__global__ __launch_bounds__(256)
void t_direct_kernel(const __half* __restrict__ Kh, const float* __restrict__ cin,
                     const float* __restrict__ esi, __half* __restrict__ Tn)
{
    const int h  = blockIdx.x;
    const int ct = blockIdx.y;
    const int b  = blockIdx.z;
    const int bh = b * 8 + h;

    const __half* kp = Kh + (size_t)b * HID * NPIX + (size_t)(h * 64) * NPIX;
    const float*  vp = cin + (size_t)b * NC * NPIX + (size_t)(ct * 64) * NPIX;

    __shared__ uint32_t As32[64][20];   // expk [d][m2]
    __shared__ uint32_t Bs32[64][20];   // cin->half [c][m2]

    const int tid = threadIdx.x;
    const int wid = tid >> 5, lid = tid & 31;
    const int g = lid >> 2, t = lid & 3;
    const int wm = (wid & 3) * 16, wn = (wid >> 2) * 32;

    const int d  = tid >> 2;
    const int m8 = (tid & 3) << 3;
    const int w0 = m8 >> 1;

    float acc[4][4];
    #pragma unroll
    for (int j = 0; j < 4; j++)
        #pragma unroll
        for (int q = 0; q < 4; q++) acc[j][q] = 0.0f;

    #pragma unroll 1
    for (int m0 = 0; m0 < NPIX; m0 += 32) {
        uint4 ka = *(const uint4*)(kp + (size_t)d * NPIX + m0 + m8);
        As32[d][w0 + 0] = ka.x; As32[d][w0 + 1] = ka.y;
        As32[d][w0 + 2] = ka.z; As32[d][w0 + 3] = ka.w;
        const float* bp = vp + (size_t)d * NPIX + m0 + m8;
        float4 b0 = *(const float4*)(bp);
        float4 b1 = *(const float4*)(bp + 4);
        __half2 h0 = __floats2half2_rn(b0.x, b0.y);
        __half2 h1 = __floats2half2_rn(b0.z, b0.w);
        __half2 h2 = __floats2half2_rn(b1.x, b1.y);
        __half2 h3 = __floats2half2_rn(b1.z, b1.w);
        Bs32[d][w0 + 0] = *(uint32_t*)&h0;
        Bs32[d][w0 + 1] = *(uint32_t*)&h1;
        Bs32[d][w0 + 2] = *(uint32_t*)&h2;
        Bs32[d][w0 + 3] = *(uint32_t*)&h3;

        __syncthreads();

        #pragma unroll
        for (int ks = 0; ks < 2; ks++) {
            const int kk2 = ks * 8;
            uint32_t af[4], bf[4][2];
            af[0] = As32[wm + g][kk2 + t];
            af[1] = As32[wm + g + 8][kk2 + t];
            af[2] = As32[wm + g][kk2 + t + 4];
            af[3] = As32[wm + g + 8][kk2 + t + 4];
            #pragma unroll
            for (int j = 0; j < 4; j++) {
                const int c = wn + j * 8 + g;
                bf[j][0] = Bs32[c][kk2 + t];
                bf[j][1] = Bs32[c][kk2 + t + 4];
            }
            #pragma unroll
            for (int j = 0; j < 4; j++)
                mma_f16(acc[j], af, bf[j]);
        }
        __syncthreads();
    }

    // normalize + write half
    __half* op = Tn + (size_t)bh * DHEAD * NC;
    const int r0 = wm + g, r1 = wm + g + 8;
    const float iv0 = esi[b * HID + h * 64 + r0];
    const float iv1 = esi[b * HID + h * 64 + r1];
    #pragma unroll
    for (int j = 0; j < 4; j++) {
        const int c = ct * 64 + wn + j * 8 + 2 * t;
        *(__half2*)(op + (size_t)r0 * NC + c) = __floats2half2_rn(acc[j][0] * iv0, acc[j][1] * iv0);
        *(__half2*)(op + (size_t)r1 * NC + c) = __floats2half2_rn(acc[j][2] * iv1, acc[j][3] * iv1);
    }
}

// ---------------- foldg: fold[b][o][h*64+d] = sum_c WW[h][o][c] * Tn[bh][d][c] ----------------
__global__ __launch_bounds__(256)
void foldg_kernel(const __half* __restrict__ WWh, const __half* __restrict__ Tn,
                  float* __restrict__ fold)
{
    const int bh = blockIdx.x;
    const int ob = blockIdx.y;
    const int b = bh >> 3, h = bh & 7;
    const __half* A = WWh + (size_t)h * NC * NC + (size_t)ob * 128 * NC;
    const __half* B = Tn + (size_t)bh * DHEAD * NC;

    __shared__ uint32_t As32[128][20];
    __shared__ uint32_t Bs32[64][20];

    const int tid = threadIdx.x;
    const int wid = tid >> 5, lid = tid & 31;
    const int g = lid >> 2, t = lid & 3;
    const int wm = wid * 16;

    const int ar = tid >> 1, ac16 = (tid & 1) * 16;
    const int br = tid >> 2, bm8 = (tid & 3) << 3;

    float acc[8][4];
    #pragma unroll
    for (int j = 0; j < 8; j++)
        #pragma unroll
        for (int q = 0; q < 4; q++) acc[j][q] = 0.0f;

    for (int k0 = 0; k0 < NC; k0 += 32) {
        uint4 a0 = *(const uint4*)(A + (size_t)ar * NC + k0 + ac16);
        uint4 a1 = *(const uint4*)(A + (size_t)ar * NC + k0 + ac16 + 8);
        const int aw = (tid & 1) * 8;
        As32[ar][aw + 0] = a0.x; As32[ar][aw + 1] = a0.y;
        As32[ar][aw + 2] = a0.z; As32[ar][aw + 3] = a0.w;
        As32[ar][aw + 4] = a1.x; As32[ar][aw + 5] = a1.y;
        As32[ar][aw + 6] = a1.z; As32[ar][aw + 7] = a1.w;
        uint4 bv = *(const uint4*)(B + (size_t)br * NC + k0 + bm8);
        const int bw = bm8 >> 1;
        Bs32[br][bw + 0] = bv.x; Bs32[br][bw + 1] = bv.y;
        Bs32[br][bw + 2] = bv.z; Bs32[br][bw + 3] = bv.w;
        __syncthreads();

        #pragma unroll
        for (int ks = 0; ks < 2; ks++) {
            const int kk2 = ks * 8;
            uint32_t af[4], bf[8][2];
            af[0] = As32[wm + g][kk2 + t];
            af[1] = As32[wm + g + 8][kk2 + t];
            af[2] = As32[wm + g][kk2 + t + 4];
            af[3] = As32[wm + g + 8][kk2 + t + 4];
            #pragma unroll
            for (int j = 0; j < 8; j++) {
                const int dc = j * 8 + g;
                bf[j][0] = Bs32[dc][kk2 + t];
                bf[j][1] = Bs32[dc][kk2 + t + 4];
            }
            #pragma unroll
            for (int j = 0; j < 8; j++)
                mma_f16(acc[j], af, bf[j]);
        }
        __syncthreads();
    }

    const int r0 = ob * 128 + wm + g;
    const int r1 = r0 + 8;
    #pragma unroll
    for (int j = 0; j < 8; j++) {
        const int dc = j * 8 + 2 * t;
        *(float2*)(fold + ((size_t)b * NC + r0) * HID + h * 64 + dc) =
            make_float2(acc[j][0], acc[j][1]);
        *(float2*)(fold + ((size_t)b * NC + r1) * HID + h * 64 + dc) =
            make_float2(acc[j][2], acc[j][3]);
    }
}

// ---------------- launch ----------------
extern "C" void kernel_launch(void* const* d_in, const int* in_sizes, int n_in,
                              void* d_out, int out_size)
{
    const float* x    = (const float*)d_in[0];
    const float* cin  = (const float*)d_in[1];
    const float* Wq   = (const float*)d_in[2];
    const float* Wk   = (const float*)d_in[3];
    const float* Wv   = (const float*)d_in[4];
    const float* Wo   = (const float*)d_in[5];
    const float* bo   = (const float*)d_in[6];
    float* out = (float*)d_out;

    __half *kh, *wkh, *wqh, *wwh, *tn;
    float *esi, *fd, *cb;
    cudaGetSymbolAddress((void**)&kh, g_kh);
    cudaGetSymbolAddress((void**)&wkh, g_wkh);
    cudaGetSymbolAddress((void**)&wqh, g_wqh);
    cudaGetSymbolAddress((void**)&wwh, g_wwh);
    cudaGetSymbolAddress((void**)&esi, g_esi);
    cudaGetSymbolAddress((void**)&tn, g_Tn);
    cudaGetSymbolAddress((void**)&fd, g_fold);
    cudaGetSymbolAddress((void**)&cb, g_comb);

    const float scale = 0.125f;

    pack_w<<<HID * NC / 256, 256>>>(Wk, Wq, wkh, wqh);

    // WW[h] = Wo_h @ Wv_h (half)
    dim3 gww(NHEAD, NC / 16);
    ww_kernel<<<gww, 256>>>(Wo, Wv, wwh);

    // k = exp(Wk @ cin) -> half (M=512, N=4096, K=256 per batch)
    dim3 gproj(NPIX / 128, HID / 128, NB);
    mma_gemm_t<1, 0, 1><<<gproj, 256>>>(wkh, 0, NC, cin, (long)NC * NPIX, NPIX,
                                        kh, (long)HID * NPIX, NPIX, nullptr, NC, 1.0f);

    // esi = 1 / row sums of expk
    es_kernel<<<NB * HID / 8, 256>>>(kh, esi);

    // Tn = normalized T, computed directly (no partials)
    dim3 gt(NHEAD, 4, NB);
    t_direct_kernel<<<gt, 256>>>(kh, cin, esi, tn);

    // fold[b][o][h*64+d] = WW[h] @ Tn[bh]^T
    dim3 gfold(NB * NHEAD, 2);
    foldg_kernel<<<gfold, 256>>>(wwh, tn, fd);

    // comb[b] = fold[b] @ (scale*Wq)  (M=256, N=256, K=512)
    dim3 gcomb(NC / 128, NC / 128, NB);
    mma_gemm_t<0, 1, 0><<<gcomb, 256>>>(fd, (long)NC * HID, HID, wqh, 0, NC,
                                        cb, (long)NC * NC, NC, nullptr, HID, scale);

    // out = comb @ x + bo  (M=256, N=4096, K=256)
    dim3 gfin(NPIX / 128, NC / 128, NB);
    mma_gemm_t<0, 0, 0><<<gfin, 256>>>(cb, (long)NC * NC, NC, x, (long)NC * NPIX, NPIX,
                                       out, (long)NC * NPIX, NPIX, bo, NC, 1.0f);
}